// round 4
// baseline (speedup 1.0000x reference)
#include <cuda_runtime.h>
#include <cuda_bf16.h>

#define NVERT 4096
#define ROW_CAP 64       // per-row neighbor cap (true max degree ~ 40; prior runs rel_err=0)
#define NB NVERT         // one block per row

// -------- device scratch (replay-idempotent: overwritten or self-wrapping) ---
__device__ float        g_pa0 [NB];
__device__ float        g_pa1 [NB];
__device__ unsigned int g_pcnt[NB];
__device__ unsigned int g_done;   // atomicInc with mod NB wraps to 0 after last block

// ---------------------------------------------------------------------------
// Single fused kernel. Block r:
//   1. streams Laplacian row r (16 KB, uint4, streaming loads, all-zero fast path)
//   2. accumulates the 12 matvec sums sub[r] (dx/x × batch × xyz) and collects
//      the neighbor list N(r) in shared
//   3. computes loss terms for all mask entries (c, r), c in N(r):
//      |‖x_sub[r]−x[c]‖² − ‖dx_sub[r]−dx[c]‖²|  (valid because L is symmetric,
//      so summing over r covers every masked entry exactly once)
//   4. writes per-block partials (overwrite); the last block reduces them and
//      writes the output. No reset kernel, no second pass over an edge list.
// ---------------------------------------------------------------------------
__global__ __launch_bounds__(256) void fused_kernel(
    const float* __restrict__ L,
    const float* __restrict__ dx,
    const float* __restrict__ x,
    float* __restrict__ out)
{
    __shared__ unsigned int s_cnt;
    __shared__ unsigned int s_list[ROW_CAP];
    __shared__ float        s_red[8][12];
    __shared__ float        s_sub[12];
    __shared__ float        s_fin[8][3];
    __shared__ bool         s_last;

    const int tid = threadIdx.x;
    if (tid == 0) s_cnt = 0u;
    __syncthreads();

    const int r = blockIdx.x;
    const uint4* __restrict__ Lrow =
        reinterpret_cast<const uint4*>(L + (size_t)r * NVERT);

    const float* __restrict__ dx1 = dx + NVERT * 3;
    const float* __restrict__ x1  = x  + NVERT * 3;

    // ---- 1+2: stream row, front-batched 4x16B loads per thread (MLP=4) ----
    uint4 v[4];
#pragma unroll
    for (int u = 0; u < 4; ++u)
        v[u] = __ldcs(&Lrow[tid + u * 256]);

    float s[12];
#pragma unroll
    for (int k = 0; k < 12; ++k) s[k] = 0.f;

#pragma unroll
    for (int u = 0; u < 4; ++u) {
        if ((v[u].x | v[u].y | v[u].z | v[u].w) != 0u) {   // rare (~0.3%)
            unsigned b[4] = {v[u].x, v[u].y, v[u].z, v[u].w};
            int j0 = (tid + u * 256) * 4;
#pragma unroll
            for (int c = 0; c < 4; ++c) {
                if (b[c] != 0u) {
                    int   j = j0 + c;
                    float w = __uint_as_float(b[c]);  // == 1.0f; multiply for exactness
                    const float* p0 = dx  + j * 3;
                    const float* p1 = dx1 + j * 3;
                    const float* q0 = x   + j * 3;
                    const float* q1 = x1  + j * 3;
                    s[0] += w * p0[0]; s[1]  += w * p0[1]; s[2]  += w * p0[2];
                    s[3] += w * p1[0]; s[4]  += w * p1[1]; s[5]  += w * p1[2];
                    s[6] += w * q0[0]; s[7]  += w * q0[1]; s[8]  += w * q0[2];
                    s[9] += w * q1[0]; s[10] += w * q1[1]; s[11] += w * q1[2];
                    unsigned pos = atomicAdd(&s_cnt, 1u);
                    if (pos < ROW_CAP) s_list[pos] = (unsigned)j;
                }
            }
        }
    }

    // ---- reduce the 12 sums across the block ----
#pragma unroll
    for (int k = 0; k < 12; ++k)
#pragma unroll
        for (int off = 16; off > 0; off >>= 1)
            s[k] += __shfl_down_sync(0xffffffffu, s[k], off);

    const int wid = tid >> 5;
    const int lid = tid & 31;
    if (lid == 0) {
#pragma unroll
        for (int k = 0; k < 12; ++k) s_red[wid][k] = s[k];
    }
    __syncthreads();
    if (tid < 12) {
        float t = 0.f;
#pragma unroll
        for (int w = 0; w < 8; ++w) t += s_red[w][tid];
        s_sub[tid] = t;   // sub[r]: [0..2] dx b0, [3..5] dx b1, [6..8] x b0, [9..11] x b1
    }
    __syncthreads();

    // ---- 3: loss terms for entries (c, r), c in N(r) ----
    const unsigned cnt = min(s_cnt, (unsigned)ROW_CAP);
    float a0 = 0.f, a1 = 0.f;
    if (tid < (int)cnt) {
        int c = (int)s_list[tid];
        // batch 0
        {
            float t0 = s_sub[0] - dx[c * 3 + 0];
            float t1 = s_sub[1] - dx[c * 3 + 1];
            float t2 = s_sub[2] - dx[c * 3 + 2];
            float u0 = s_sub[6] - x [c * 3 + 0];
            float u1 = s_sub[7] - x [c * 3 + 1];
            float u2 = s_sub[8] - x [c * 3 + 2];
            a0 = fabsf((u0*u0 + u1*u1 + u2*u2) - (t0*t0 + t1*t1 + t2*t2));
        }
        // batch 1
        {
            float t0 = s_sub[3]  - dx1[c * 3 + 0];
            float t1 = s_sub[4]  - dx1[c * 3 + 1];
            float t2 = s_sub[5]  - dx1[c * 3 + 2];
            float u0 = s_sub[9]  - x1 [c * 3 + 0];
            float u1 = s_sub[10] - x1 [c * 3 + 1];
            float u2 = s_sub[11] - x1 [c * 3 + 2];
            a1 = fabsf((u0*u0 + u1*u1 + u2*u2) - (t0*t0 + t1*t1 + t2*t2));
        }
    }
    // block reduce (only warps 0/1 can carry nonzero, but full reduce is cheap)
#pragma unroll
    for (int off = 16; off > 0; off >>= 1) {
        a0 += __shfl_down_sync(0xffffffffu, a0, off);
        a1 += __shfl_down_sync(0xffffffffu, a1, off);
    }
    if (lid == 0) { s_fin[wid][0] = a0; s_fin[wid][1] = a1; }
    __syncthreads();
    if (tid == 0) {
        float t0 = 0.f, t1 = 0.f;
#pragma unroll
        for (int w = 0; w < 8; ++w) { t0 += s_fin[w][0]; t1 += s_fin[w][1]; }
        g_pa0 [r] = t0;          // overwrite: no reset needed across replays
        g_pa1 [r] = t1;
        g_pcnt[r] = cnt;
    }

    // ---- 4: last-block finalize (g_done self-wraps to 0) ----
    __threadfence();
    if (tid == 0)
        s_last = (atomicInc(&g_done, NB - 1) == NB - 1);
    __syncthreads();

    if (s_last) {
        float t0 = 0.f, t1 = 0.f, tc = 0.f;
        for (int k = tid; k < NB; k += 256) {
            t0 += __ldcg(&g_pa0[k]);                 // .cg: bypass (possibly stale) L1
            t1 += __ldcg(&g_pa1[k]);
            tc += (float)__ldcg(&g_pcnt[k]);
        }
#pragma unroll
        for (int off = 16; off > 0; off >>= 1) {
            t0 += __shfl_down_sync(0xffffffffu, t0, off);
            t1 += __shfl_down_sync(0xffffffffu, t1, off);
            tc += __shfl_down_sync(0xffffffffu, tc, off);
        }
        if (lid == 0) { s_fin[wid][0] = t0; s_fin[wid][1] = t1; s_fin[wid][2] = tc; }
        __syncthreads();
        if (tid == 0) {
            float f0 = 0.f, f1 = 0.f, n = 0.f;
#pragma unroll
            for (int w = 0; w < 8; ++w) {
                f0 += s_fin[w][0]; f1 += s_fin[w][1]; n += s_fin[w][2];
            }
            out[0] = f0 / n;
            out[1] = f1 / n;
        }
    }
}

// -------- launch -------------------------------------------------------------
extern "C" void kernel_launch(void* const* d_in, const int* in_sizes, int n_in,
                              void* d_out, int out_size) {
    const float* lap = nullptr;
    const float* vecs[2] = {nullptr, nullptr};
    int vn = 0;
    for (int k = 0; k < n_in; ++k) {
        if (in_sizes[k] == NVERT * NVERT)
            lap = (const float*)d_in[k];
        else if (vn < 2)
            vecs[vn++] = (const float*)d_in[k];
    }
    if (!lap && n_in >= 3) lap = (const float*)d_in[2];
    const float* dx = vecs[0] ? vecs[0] : (const float*)d_in[0];
    const float* x  = vecs[1] ? vecs[1] : (const float*)d_in[1];
    float* out = (float*)d_out;

    fused_kernel<<<NB, 256>>>(lap, dx, x, out);
}

// round 6
// speedup vs baseline: 1.3842x; 1.3842x over previous
#include <cuda_runtime.h>
#include <cuda_bf16.h>

#define NVERT 4096
#define ROW_CAP 64            // per-row neighbor cap (true max degree ~ 40)
#define WPB 8                 // warps per block
#define NBLOCKS (NVERT / WPB) // 512: one warp per row, single wave

// -------- device scratch (pure overwrite each launch: replay-idempotent) ----
__device__ float        g_pa0 [NVERT];
__device__ float        g_pa1 [NVERT];
__device__ unsigned int g_pcnt[NVERT];

// ---------------------------------------------------------------------------
// Kernel 1: warp-per-row fused scan + loss.
// Warp w owns Laplacian row r. Each lane streams 32 coalesced float4
// (4 batches of 8, MLP=8, streaming .cs loads). Nonzeros (~12/row total) feed
// 12 matvec accumulators and a per-warp shared neighbor list. Warp
// butterfly-reduces the 12 sums (all lanes get totals), lanes compute the
// loss terms for mask entries (c, r) — coverage is exact because L is
// symmetric, so iterating rows covers every masked entry exactly once
// (including diagonal self-loops). Lane 0 overwrites per-row partials.
// No block syncs, no fences, no global atomics.
// ---------------------------------------------------------------------------
__global__ __launch_bounds__(256) void scan_kernel(
    const float* __restrict__ L,
    const float* __restrict__ dx,
    const float* __restrict__ x)
{
    __shared__ unsigned int s_cnt [WPB];
    __shared__ unsigned int s_list[WPB][ROW_CAP];

    const int wid  = threadIdx.x >> 5;
    const int lane = threadIdx.x & 31;
    if (lane == 0) s_cnt[wid] = 0u;
    __syncwarp();

    const int r = blockIdx.x * WPB + wid;
    const uint4* __restrict__ Lrow =
        reinterpret_cast<const uint4*>(L + (size_t)r * NVERT);

    const float* __restrict__ dx1 = dx + NVERT * 3;
    const float* __restrict__ x1  = x  + NVERT * 3;

    float s[12];
#pragma unroll
    for (int k = 0; k < 12; ++k) s[k] = 0.f;

    // 1024 float4 per row / 32 lanes = 32 per lane; 4 batches of 8 (MLP=8)
#pragma unroll
    for (int kb = 0; kb < 4; ++kb) {
        uint4 v[8];
#pragma unroll
        for (int m = 0; m < 8; ++m)
            v[m] = __ldcs(&Lrow[lane + (kb * 8 + m) * 32]);

#pragma unroll
        for (int m = 0; m < 8; ++m) {
            if ((v[m].x | v[m].y | v[m].z | v[m].w) != 0u) {  // rare (~0.3%)
                unsigned b[4] = {v[m].x, v[m].y, v[m].z, v[m].w};
                int j0 = (lane + (kb * 8 + m) * 32) * 4;
#pragma unroll
                for (int c = 0; c < 4; ++c) {
                    if (b[c] != 0u) {
                        int   j = j0 + c;
                        float w = __uint_as_float(b[c]);  // == 1.0f; mul for exactness
                        const float* p0 = dx  + j * 3;
                        const float* p1 = dx1 + j * 3;
                        const float* q0 = x   + j * 3;
                        const float* q1 = x1  + j * 3;
                        s[0] += w * p0[0]; s[1]  += w * p0[1]; s[2]  += w * p0[2];
                        s[3] += w * p1[0]; s[4]  += w * p1[1]; s[5]  += w * p1[2];
                        s[6] += w * q0[0]; s[7]  += w * q0[1]; s[8]  += w * q0[2];
                        s[9] += w * q1[0]; s[10] += w * q1[1]; s[11] += w * q1[2];
                        unsigned pos = atomicAdd(&s_cnt[wid], 1u);
                        if (pos < ROW_CAP) s_list[wid][pos] = (unsigned)j;
                    }
                }
            }
        }
    }

    // ---- warp butterfly reduce: every lane ends with the full 12 sums ----
#pragma unroll
    for (int k = 0; k < 12; ++k)
#pragma unroll
        for (int off = 16; off > 0; off >>= 1)
            s[k] += __shfl_xor_sync(0xffffffffu, s[k], off);
    __syncwarp();

    const unsigned cnt = min(s_cnt[wid], (unsigned)ROW_CAP);

    // ---- loss terms for this row's neighbors (degree may exceed 32) ----
    float a0 = 0.f, a1 = 0.f;
    for (unsigned k = lane; k < cnt; k += 32) {
        int c = (int)s_list[wid][k];
        // batch 0
        {
            float t0 = s[0] - dx[c * 3 + 0];
            float t1 = s[1] - dx[c * 3 + 1];
            float t2 = s[2] - dx[c * 3 + 2];
            float u0 = s[6] - x [c * 3 + 0];
            float u1 = s[7] - x [c * 3 + 1];
            float u2 = s[8] - x [c * 3 + 2];
            a0 += fabsf((u0*u0 + u1*u1 + u2*u2) - (t0*t0 + t1*t1 + t2*t2));
        }
        // batch 1
        {
            float t0 = s[3]  - dx1[c * 3 + 0];
            float t1 = s[4]  - dx1[c * 3 + 1];
            float t2 = s[5]  - dx1[c * 3 + 2];
            float u0 = s[9]  - x1 [c * 3 + 0];
            float u1 = s[10] - x1 [c * 3 + 1];
            float u2 = s[11] - x1 [c * 3 + 2];
            a1 += fabsf((u0*u0 + u1*u1 + u2*u2) - (t0*t0 + t1*t1 + t2*t2));
        }
    }
#pragma unroll
    for (int off = 16; off > 0; off >>= 1) {
        a0 += __shfl_down_sync(0xffffffffu, a0, off);
        a1 += __shfl_down_sync(0xffffffffu, a1, off);
    }
    if (lane == 0) {
        g_pa0 [r] = a0;       // plain overwrite; kernel boundary publishes it
        g_pa1 [r] = a1;
        g_pcnt[r] = cnt;
    }
}

// ---------------------------------------------------------------------------
// Kernel 2: single-block finalize over the 4096 per-row partials (L2-hot).
// ---------------------------------------------------------------------------
__global__ __launch_bounds__(256) void finalize_kernel(float* __restrict__ out)
{
    const int tid = threadIdx.x;
    float t0 = 0.f, t1 = 0.f, tc = 0.f;
    for (int k = tid; k < NVERT; k += 256) {
        t0 += g_pa0[k];
        t1 += g_pa1[k];
        tc += (float)g_pcnt[k];   // n_edges <= 49152: exact in fp32
    }
#pragma unroll
    for (int off = 16; off > 0; off >>= 1) {
        t0 += __shfl_down_sync(0xffffffffu, t0, off);
        t1 += __shfl_down_sync(0xffffffffu, t1, off);
        tc += __shfl_down_sync(0xffffffffu, tc, off);
    }
    __shared__ float sa[8][3];
    const int wid = tid >> 5;
    const int lid = tid & 31;
    if (lid == 0) { sa[wid][0] = t0; sa[wid][1] = t1; sa[wid][2] = tc; }
    __syncthreads();
    if (tid == 0) {
        float f0 = 0.f, f1 = 0.f, n = 0.f;
#pragma unroll
        for (int w = 0; w < 8; ++w) {
            f0 += sa[w][0]; f1 += sa[w][1]; n += sa[w][2];
        }
        out[0] = f0 / n;
        out[1] = f1 / n;
    }
}

// -------- launch -------------------------------------------------------------
extern "C" void kernel_launch(void* const* d_in, const int* in_sizes, int n_in,
                              void* d_out, int out_size) {
    const float* lap = nullptr;
    const float* vecs[2] = {nullptr, nullptr};
    int vn = 0;
    for (int k = 0; k < n_in; ++k) {
        if (in_sizes[k] == NVERT * NVERT)
            lap = (const float*)d_in[k];
        else if (vn < 2)
            vecs[vn++] = (const float*)d_in[k];
    }
    if (!lap && n_in >= 3) lap = (const float*)d_in[2];
    const float* dx = vecs[0] ? vecs[0] : (const float*)d_in[0];
    const float* x  = vecs[1] ? vecs[1] : (const float*)d_in[1];
    float* out = (float*)d_out;

    scan_kernel<<<NBLOCKS, 256>>>(lap, dx, x);
    finalize_kernel<<<1, 256>>>(out);
}

// round 7
// speedup vs baseline: 1.7235x; 1.2451x over previous
#include <cuda_runtime.h>
#include <cuda_bf16.h>

#define NVERT 4096
#define ROW_CAP 64            // per-row neighbor cap (true max degree ~ 40)
#define WPB 8                 // warps per block
#define NBLOCKS (NVERT / WPB) // 512: one warp per row, single wave

// -------- device scratch (pure overwrite each launch: replay-idempotent) ----
__device__ float g_pb0 [NBLOCKS];   // per-BLOCK partials (512 entries)
__device__ float g_pb1 [NBLOCKS];
__device__ float g_pbc [NBLOCKS];

// ---------------------------------------------------------------------------
// Kernel 1: warp-per-row fused scan + loss, block-level partial reduction.
// Warp w owns Laplacian row r: streams 32 coalesced float4/lane (4 batches
// of 8, MLP=8, .cs), nonzeros (~12/row) feed 12 matvec accumulators and a
// per-warp shared neighbor list. Warp butterfly gives all lanes sub[r];
// lanes compute loss terms for mask entries (c, r) — exact coverage since L
// is symmetric. The 8 warps' partials then fold through shared memory into
// ONE (a0, a1, cnt) triple per block, overwritten into 512-entry arrays.
// No fences, no global atomics, no reset state.
// ---------------------------------------------------------------------------
__global__ __launch_bounds__(256) void scan_kernel(
    const float* __restrict__ L,
    const float* __restrict__ dx,
    const float* __restrict__ x)
{
    __shared__ unsigned int s_cnt [WPB];
    __shared__ unsigned int s_list[WPB][ROW_CAP];
    __shared__ float        s_par [WPB][3];

    const int wid  = threadIdx.x >> 5;
    const int lane = threadIdx.x & 31;
    if (lane == 0) s_cnt[wid] = 0u;
    __syncwarp();

    const int r = blockIdx.x * WPB + wid;
    const uint4* __restrict__ Lrow =
        reinterpret_cast<const uint4*>(L + (size_t)r * NVERT);

    const float* __restrict__ dx1 = dx + NVERT * 3;
    const float* __restrict__ x1  = x  + NVERT * 3;

    float s[12];
#pragma unroll
    for (int k = 0; k < 12; ++k) s[k] = 0.f;

    // 1024 float4 per row / 32 lanes = 32 per lane; 4 batches of 8 (MLP=8)
#pragma unroll
    for (int kb = 0; kb < 4; ++kb) {
        uint4 v[8];
#pragma unroll
        for (int m = 0; m < 8; ++m)
            v[m] = __ldcs(&Lrow[lane + (kb * 8 + m) * 32]);

#pragma unroll
        for (int m = 0; m < 8; ++m) {
            if ((v[m].x | v[m].y | v[m].z | v[m].w) != 0u) {  // rare (~0.3%)
                unsigned b[4] = {v[m].x, v[m].y, v[m].z, v[m].w};
                int j0 = (lane + (kb * 8 + m) * 32) * 4;
#pragma unroll
                for (int c = 0; c < 4; ++c) {
                    if (b[c] != 0u) {
                        int   j = j0 + c;
                        float w = __uint_as_float(b[c]);  // == 1.0f; mul for exactness
                        const float* p0 = dx  + j * 3;
                        const float* p1 = dx1 + j * 3;
                        const float* q0 = x   + j * 3;
                        const float* q1 = x1  + j * 3;
                        s[0] += w * p0[0]; s[1]  += w * p0[1]; s[2]  += w * p0[2];
                        s[3] += w * p1[0]; s[4]  += w * p1[1]; s[5]  += w * p1[2];
                        s[6] += w * q0[0]; s[7]  += w * q0[1]; s[8]  += w * q0[2];
                        s[9] += w * q1[0]; s[10] += w * q1[1]; s[11] += w * q1[2];
                        unsigned pos = atomicAdd(&s_cnt[wid], 1u);
                        if (pos < ROW_CAP) s_list[wid][pos] = (unsigned)j;
                    }
                }
            }
        }
    }

    // ---- warp butterfly reduce: every lane ends with the full 12 sums ----
#pragma unroll
    for (int k = 0; k < 12; ++k)
#pragma unroll
        for (int off = 16; off > 0; off >>= 1)
            s[k] += __shfl_xor_sync(0xffffffffu, s[k], off);
    __syncwarp();

    const unsigned cnt = min(s_cnt[wid], (unsigned)ROW_CAP);

    // ---- loss terms for this row's neighbors (degree may exceed 32) ----
    float a0 = 0.f, a1 = 0.f;
    for (unsigned k = lane; k < cnt; k += 32) {
        int c = (int)s_list[wid][k];
        // batch 0
        {
            float t0 = s[0] - dx[c * 3 + 0];
            float t1 = s[1] - dx[c * 3 + 1];
            float t2 = s[2] - dx[c * 3 + 2];
            float u0 = s[6] - x [c * 3 + 0];
            float u1 = s[7] - x [c * 3 + 1];
            float u2 = s[8] - x [c * 3 + 2];
            a0 += fabsf((u0*u0 + u1*u1 + u2*u2) - (t0*t0 + t1*t1 + t2*t2));
        }
        // batch 1
        {
            float t0 = s[3]  - dx1[c * 3 + 0];
            float t1 = s[4]  - dx1[c * 3 + 1];
            float t2 = s[5]  - dx1[c * 3 + 2];
            float u0 = s[9]  - x1 [c * 3 + 0];
            float u1 = s[10] - x1 [c * 3 + 1];
            float u2 = s[11] - x1 [c * 3 + 2];
            a1 += fabsf((u0*u0 + u1*u1 + u2*u2) - (t0*t0 + t1*t1 + t2*t2));
        }
    }
#pragma unroll
    for (int off = 16; off > 0; off >>= 1) {
        a0 += __shfl_down_sync(0xffffffffu, a0, off);
        a1 += __shfl_down_sync(0xffffffffu, a1, off);
    }
    if (lane == 0) {
        s_par[wid][0] = a0;
        s_par[wid][1] = a1;
        s_par[wid][2] = (float)cnt;
    }
    __syncthreads();

    // ---- fold 8 warp partials -> one per-block triple (overwrite) ----
    if (threadIdx.x == 0) {
        float t0 = 0.f, t1 = 0.f, tc = 0.f;
#pragma unroll
        for (int w = 0; w < WPB; ++w) {
            t0 += s_par[w][0]; t1 += s_par[w][1]; tc += s_par[w][2];
        }
        g_pb0[blockIdx.x] = t0;
        g_pb1[blockIdx.x] = t1;
        g_pbc[blockIdx.x] = tc;
    }
}

// ---------------------------------------------------------------------------
// Kernel 2: finalize over 512 per-block partials — one load per thread,
// everything in flight at once, L2-hot.
// ---------------------------------------------------------------------------
__global__ __launch_bounds__(512) void finalize_kernel(float* __restrict__ out)
{
    const int tid = threadIdx.x;
    float t0 = g_pb0[tid];
    float t1 = g_pb1[tid];
    float tc = g_pbc[tid];

#pragma unroll
    for (int off = 16; off > 0; off >>= 1) {
        t0 += __shfl_down_sync(0xffffffffu, t0, off);
        t1 += __shfl_down_sync(0xffffffffu, t1, off);
        tc += __shfl_down_sync(0xffffffffu, tc, off);
    }
    __shared__ float sa[16][3];
    const int wid = tid >> 5;
    const int lid = tid & 31;
    if (lid == 0) { sa[wid][0] = t0; sa[wid][1] = t1; sa[wid][2] = tc; }
    __syncthreads();
    if (tid == 0) {
        float f0 = 0.f, f1 = 0.f, n = 0.f;
#pragma unroll
        for (int w = 0; w < 16; ++w) {
            f0 += sa[w][0]; f1 += sa[w][1]; n += sa[w][2];
        }
        out[0] = f0 / n;
        out[1] = f1 / n;
    }
}

// -------- launch -------------------------------------------------------------
extern "C" void kernel_launch(void* const* d_in, const int* in_sizes, int n_in,
                              void* d_out, int out_size) {
    const float* lap = nullptr;
    const float* vecs[2] = {nullptr, nullptr};
    int vn = 0;
    for (int k = 0; k < n_in; ++k) {
        if (in_sizes[k] == NVERT * NVERT)
            lap = (const float*)d_in[k];
        else if (vn < 2)
            vecs[vn++] = (const float*)d_in[k];
    }
    if (!lap && n_in >= 3) lap = (const float*)d_in[2];
    const float* dx = vecs[0] ? vecs[0] : (const float*)d_in[0];
    const float* x  = vecs[1] ? vecs[1] : (const float*)d_in[1];
    float* out = (float*)d_out;

    scan_kernel<<<NBLOCKS, 256>>>(lap, dx, x);
    finalize_kernel<<<1, 512>>>(out);
}